// round 3
// baseline (speedup 1.0000x reference)
#include <cuda_runtime.h>
#include <cuda_fp16.h>

#define NN 4096
#define SB 4

// Scratch (allocation-free requirement => __device__ globals)
__device__ __align__(16) __half g_E [(size_t)NN * NN];   // exp(-C/eps),        row-major [n][m]
__device__ __align__(16) __half g_Et[(size_t)NN * NN];   // exp(-C/eps)^T,      row-major [m][n]
__device__ __align__(16) float  g_u [SB * NN];           // exp(g/eps), planes [s][m]
__device__ __align__(16) float  g_v [SB * NN];           // exp(f/eps), planes [s][n]

// ---------------------------------------------------------------------------
// u0 = exp(g0/eps) = 1
__global__ void init_u_kernel() {
    int i = blockIdx.x * blockDim.x + threadIdx.x;
    if (i < SB * NN) g_u[i] = 1.0f;
}

// ---------------------------------------------------------------------------
// K = exp(-C/eps) in fp16, plus transposed copy (smem tile transpose).
__global__ __launch_bounds__(256) void prep_kernel(const float* __restrict__ C,
                                                   const float* __restrict__ eps_p) {
    __shared__ __half tile[32][33];  // 33-pad => conflict-free column reads
    const float scale = -1.4426950408889634f / eps_p[0];  // exp(-c/eps) = exp2(c*scale)
    const int tx = threadIdx.x, ty = threadIdx.y;
    const int x  = blockIdx.x * 32 + tx;
    const int yb = blockIdx.y * 32;
#pragma unroll
    for (int j = 0; j < 32; j += 8) {
        int y = yb + ty + j;
        float c = __ldg(&C[(size_t)y * NN + x]);
        __half h = __float2half(exp2f(c * scale));
        g_E[(size_t)y * NN + x] = h;
        tile[ty + j][tx] = h;
    }
    __syncthreads();
    const int x2  = blockIdx.y * 32 + tx;
    const int yb2 = blockIdx.x * 32;
#pragma unroll
    for (int j = 0; j < 32; j += 8) {
        // g_Et[m][n] = g_E[n][m]
        g_Et[(size_t)(yb2 + ty + j) * NN + x2] = tile[tx][ty + j];
    }
}

// ---------------------------------------------------------------------------
// One Sinkhorn half-step:  xout[s][n] = ab[s][n] / sum_m M[n][m] * xin[s][m]
// dir==0: M=g_E,  xin=g_u, xout=g_v, ab=alpha   (f-step)
// dir==1: M=g_Et, xin=g_v, xout=g_u, ab=beta    (g-step)
//
// 128 blocks x 256 threads; each warp register-blocks 4 rows x 4 batches,
// accumulating with packed fma.rn.f32x2 (even/odd m lanes in one 64-bit reg).
// E is streamed through L1 with __ldcs so the 64KB xin vectors stay L1-hot.
__global__ __launch_bounds__(256) void pass_kernel(int dir, const float* __restrict__ ab) {
    const __half* Mh  = dir ? g_Et : g_E;
    const float*  xin = dir ? g_v  : g_u;
    float*        xout = dir ? g_u : g_v;

    const int warp = threadIdx.x >> 5;
    const int lane = threadIdx.x & 31;
    const int row0 = blockIdx.x * 32 + warp * 4;  // 4 rows per warp, 32 per block

    const __half2* m0 = reinterpret_cast<const __half2*>(Mh + (size_t)row0 * NN);

    unsigned long long acc[4][4];
#pragma unroll
    for (int r = 0; r < 4; r++)
#pragma unroll
        for (int s = 0; s < 4; s++) acc[r][s] = 0ull;  // (0.0f, 0.0f)

#pragma unroll 2
    for (int i = lane; i < NN / 2; i += 32) {
        unsigned long long us[4];
#pragma unroll
        for (int s = 0; s < 4; s++)  // (xin[s][2i], xin[s][2i+1]) as packed f32x2
            us[s] = *reinterpret_cast<const unsigned long long*>(xin + s * NN + 2 * i);
#pragma unroll
        for (int r = 0; r < 4; r++) {
            __half2 h = __ldcs(m0 + (size_t)r * (NN / 2) + i);  // streaming, evict-first
            float2 e = __half22float2(h);
            unsigned long long e2;
            asm("mov.b64 %0, {%1, %2};" : "=l"(e2) : "f"(e.x), "f"(e.y));
#pragma unroll
            for (int s = 0; s < 4; s++)
                asm("fma.rn.f32x2 %0, %1, %2, %0;"
                    : "+l"(acc[r][s]) : "l"(e2), "l"(us[s]));
        }
    }

    // reduce: even+odd halves, then warp shuffle; fuse the division
#pragma unroll
    for (int r = 0; r < 4; r++) {
#pragma unroll
        for (int s = 0; s < 4; s++) {
            float lo, hi;
            asm("mov.b64 {%0, %1}, %2;" : "=f"(lo), "=f"(hi) : "l"(acc[r][s]));
            float t = lo + hi;
#pragma unroll
            for (int o = 16; o; o >>= 1) t += __shfl_down_sync(0xffffffffu, t, o);
            if (lane == 0) {
                int n = row0 + r;
                xout[s * NN + n] = ab[s * NN + n] / t;
            }
        }
    }
}

// ---------------------------------------------------------------------------
// f = eps*log(v), g = eps*log(u); planes [s][n] already match output layout.
__global__ void final_kernel(float* __restrict__ out, const float* __restrict__ eps_p) {
    int i = blockIdx.x * blockDim.x + threadIdx.x;
    float eps = eps_p[0];
    if (i < SB * NN) {
        out[i]           = eps * __logf(g_v[i]);  // f
        out[SB * NN + i] = eps * __logf(g_u[i]);  // g
    }
}

// ---------------------------------------------------------------------------
extern "C" void kernel_launch(void* const* d_in, const int* in_sizes, int n_in,
                              void* d_out, int out_size) {
    const float* alpha = (const float*)d_in[0];  // (4, 4096)
    const float* beta  = (const float*)d_in[1];  // (4, 4096)
    const float* C     = (const float*)d_in[2];  // (4096, 4096)
    const float* eps   = (const float*)d_in[3];  // scalar
    float* out = (float*)d_out;                  // f (4,4096) then g (4,4096)

    init_u_kernel<<<(SB * NN + 255) / 256, 256>>>();

    dim3 pb(32, 8), pg(NN / 32, NN / 32);
    prep_kernel<<<pg, pb>>>(C, eps);

    for (int it = 0; it < 10; it++) {
        pass_kernel<<<NN / 32, 256>>>(0, alpha);  // v = alpha / (K  u)
        pass_kernel<<<NN / 32, 256>>>(1, beta);   // u = beta  / (K^T v)
    }

    final_kernel<<<(SB * NN + 255) / 256, 256>>>(out, eps);
}

// round 5
// speedup vs baseline: 1.8106x; 1.8106x over previous
#include <cuda_runtime.h>
#include <cuda_fp16.h>
#include <stdint.h>

#define NN 4096
#define SB 4

#define TR 16                       // rows per block tile
#define CK 1024                     // cols per chunk
#define NCHUNK (NN / CK)            // 4
#define STAGES 3
#define CW 4                        // consumer warps
#define THREADS ((CW + 1) * 32)     // 160: 4 consumer warps + 1 producer warp
#define STAGE_BYTES (TR * CK * 2)   // 32 KB
#define SMEM_BYTES (STAGES * STAGE_BYTES)  // 96 KB

// Scratch (allocation-free requirement => __device__ globals)
__device__ __align__(16) __half g_E [(size_t)NN * NN];   // exp(-C/eps)    [n][m]
__device__ __align__(16) __half g_Et[(size_t)NN * NN];   // transpose      [m][n]
__device__ __align__(16) float  g_u [SB * NN];
__device__ __align__(16) float  g_v [SB * NN];

// ---------------------------------------------------------------------------
__device__ __forceinline__ uint32_t s2u(const void* p) {
    uint32_t a;
    asm("{ .reg .u64 t; cvta.to.shared.u64 t, %1; cvt.u32.u64 %0, t; }" : "=r"(a) : "l"(p));
    return a;
}
#define MB_INIT(a, c)  asm volatile("mbarrier.init.shared.b64 [%0], %1;" :: "r"(a), "r"(c) : "memory")
#define MB_EXPECT(a, b) asm volatile("mbarrier.arrive.expect_tx.shared.b64 _, [%0], %1;" :: "r"(a), "r"(b) : "memory")
#define MB_ARRIVE(a)   asm volatile("mbarrier.arrive.shared.b64 _, [%0];" :: "r"(a) : "memory")
#define MB_WAIT(a, p) do {                                                              \
    uint32_t _done;                                                                     \
    asm volatile("{\n\t.reg .pred P;\n\t"                                               \
        "mbarrier.try_wait.parity.acquire.cta.shared::cta.b64 P, [%1], %2;\n\t"         \
        "selp.b32 %0, 1, 0, P;\n\t}"                                                    \
        : "=r"(_done) : "r"(a), "r"(p) : "memory");                                     \
    while (!_done) {                                                                    \
        asm volatile("{\n\t.reg .pred P;\n\t"                                           \
            "mbarrier.try_wait.parity.acquire.cta.shared::cta.b64 P, [%1], %2, 0x989680;\n\t" \
            "selp.b32 %0, 1, 0, P;\n\t}"                                                \
            : "=r"(_done) : "r"(a), "r"(p) : "memory");                                 \
    }                                                                                   \
} while (0)

__device__ __forceinline__ void bulk_g2s(uint32_t dst, const void* src, uint32_t bytes, uint32_t mbar) {
    asm volatile("cp.async.bulk.shared::cta.global.mbarrier::complete_tx::bytes [%0], [%1], %2, [%3];"
                 :: "r"(dst), "l"(src), "r"(bytes), "r"(mbar) : "memory");
}

// ---------------------------------------------------------------------------
// u0 = exp(g0/eps) = 1
__global__ void init_u_kernel() {
    int i = blockIdx.x * blockDim.x + threadIdx.x;
    if (i < SB * NN) g_u[i] = 1.0f;
}

// ---------------------------------------------------------------------------
// K = exp(-C/eps) in fp16, plus transposed copy (smem tile transpose).
__global__ __launch_bounds__(256) void prep_kernel(const float* __restrict__ C,
                                                   const float* __restrict__ eps_p) {
    __shared__ __half tile[32][33];
    const float scale = -1.4426950408889634f / eps_p[0];
    const int tx = threadIdx.x, ty = threadIdx.y;
    const int x  = blockIdx.x * 32 + tx;
    const int yb = blockIdx.y * 32;
#pragma unroll
    for (int j = 0; j < 32; j += 8) {
        int y = yb + ty + j;
        float c = __ldg(&C[(size_t)y * NN + x]);
        __half h = __float2half(exp2f(c * scale));
        g_E[(size_t)y * NN + x] = h;
        tile[ty + j][tx] = h;
    }
    __syncthreads();
    const int x2  = blockIdx.y * 32 + tx;
    const int yb2 = blockIdx.x * 32;
#pragma unroll
    for (int j = 0; j < 32; j += 8)
        g_Et[(size_t)(yb2 + ty + j) * NN + x2] = tile[tx][ty + j];
}

// ---------------------------------------------------------------------------
// One Sinkhorn half-step:  xout[s][n] = ab[s][n] / sum_m M[n][m] * xin[s][m]
// E streamed via cp.async.bulk into a 3-stage smem pipeline (producer warp),
// consumed by 4 warps x 4 rows with packed fma.rn.f32x2.
__global__ __launch_bounds__(THREADS) void pass_kernel(int dir, const float* __restrict__ ab) {
    extern __shared__ __align__(128) unsigned char smem[];
    __shared__ __align__(8) unsigned long long mb[2 * STAGES];  // full[0..2], empty[3..5]

    const __half* Mh   = dir ? g_Et : g_E;
    const float*  xin  = dir ? g_v  : g_u;
    float*        xout = dir ? g_u  : g_v;

    const uint32_t sbase = s2u(smem);
    const uint32_t mbase = s2u(mb);
    const int tid  = threadIdx.x;
    const int warp = tid >> 5;
    const int lane = tid & 31;
    const int row0 = blockIdx.x * TR;

    if (tid == 0) {
#pragma unroll
        for (int s = 0; s < STAGES; s++) {
            MB_INIT(mbase + s * 8, 1);              // full: expect_tx arrive
            MB_INIT(mbase + (STAGES + s) * 8, CW);  // empty: one arrive per consumer warp
        }
        asm volatile("fence.proxy.async.shared::cta;" ::: "memory");
    }
    __syncthreads();

    if (warp == CW) {
        // ---- producer: single thread drives TMA bulk copies ----
        if (lane == 0) {
            int st = 0, ph = 1;  // empty-waits pass immediately on fresh barriers
            const char* base = (const char*)Mh + (size_t)row0 * NN * 2;
            for (int c = 0; c < NCHUNK; c++) {
                MB_WAIT(mbase + (STAGES + st) * 8, ph);
                MB_EXPECT(mbase + st * 8, STAGE_BYTES);
                const char* src = base + (size_t)c * CK * 2;
                uint32_t dst = sbase + st * STAGE_BYTES;
#pragma unroll
                for (int r = 0; r < TR; r++)
                    bulk_g2s(dst + r * (CK * 2), src + (size_t)r * NN * 2, CK * 2, mbase + st * 8);
                if (++st == STAGES) { st = 0; ph ^= 1; }
            }
        }
        return;
    }

    // ---- consumer: warp handles 4 rows, registers block 4 batches ----
    unsigned long long acc[4][4];
#pragma unroll
    for (int r = 0; r < 4; r++)
#pragma unroll
        for (int s = 0; s < 4; s++) acc[r][s] = 0ull;

    int st = 0, ph = 0;
    for (int c = 0; c < NCHUNK; c++) {
        MB_WAIT(mbase + st * 8, ph);
        const unsigned char* tile = smem + st * STAGE_BYTES + (warp * 4) * (CK * 2);
        const float* uc = xin + c * CK;

#pragma unroll 4
        for (int k = 0; k < CK / (32 * 4); k++) {   // 8 steps, 4 cols/lane/step
            const int ci = (k * 32 + lane) * 4;     // col within chunk

            unsigned long long u01[SB], u23[SB];
#pragma unroll
            for (int s = 0; s < SB; s++) {
                float4 uv = *reinterpret_cast<const float4*>(uc + s * NN + ci);
                asm("mov.b64 %0, {%1, %2};" : "=l"(u01[s]) : "f"(uv.x), "f"(uv.y));
                asm("mov.b64 %0, {%1, %2};" : "=l"(u23[s]) : "f"(uv.z), "f"(uv.w));
            }
#pragma unroll
            for (int r = 0; r < 4; r++) {
                uint2 hh = *reinterpret_cast<const uint2*>(tile + r * (CK * 2) + ci * 2);  // LDS.64
                float2 f01 = __half22float2(*reinterpret_cast<const __half2*>(&hh.x));
                float2 f23 = __half22float2(*reinterpret_cast<const __half2*>(&hh.y));
                unsigned long long e01, e23;
                asm("mov.b64 %0, {%1, %2};" : "=l"(e01) : "f"(f01.x), "f"(f01.y));
                asm("mov.b64 %0, {%1, %2};" : "=l"(e23) : "f"(f23.x), "f"(f23.y));
#pragma unroll
                for (int s = 0; s < SB; s++) {
                    asm("fma.rn.f32x2 %0, %1, %2, %0;" : "+l"(acc[r][s]) : "l"(e01), "l"(u01[s]));
                    asm("fma.rn.f32x2 %0, %1, %2, %0;" : "+l"(acc[r][s]) : "l"(e23), "l"(u23[s]));
                }
            }
        }
        __syncwarp();
        if (lane == 0) MB_ARRIVE(mbase + (STAGES + st) * 8);
        if (++st == STAGES) { st = 0; ph ^= 1; }
    }

    // reduce: packed halves, then warp shuffle; fuse the division
#pragma unroll
    for (int r = 0; r < 4; r++) {
#pragma unroll
        for (int s = 0; s < 4; s++) {
            float lo, hi;
            asm("mov.b64 {%0, %1}, %2;" : "=f"(lo), "=f"(hi) : "l"(acc[r][s]));
            float t = lo + hi;
#pragma unroll
            for (int o = 16; o; o >>= 1) t += __shfl_down_sync(0xffffffffu, t, o);
            if (lane == 0) {
                int n = row0 + warp * 4 + r;
                xout[s * NN + n] = ab[s * NN + n] / t;
            }
        }
    }
}

// ---------------------------------------------------------------------------
// f = eps*log(v), g = eps*log(u)
__global__ void final_kernel(float* __restrict__ out, const float* __restrict__ eps_p) {
    int i = blockIdx.x * blockDim.x + threadIdx.x;
    float eps = eps_p[0];
    if (i < SB * NN) {
        out[i]           = eps * __logf(g_v[i]);  // f
        out[SB * NN + i] = eps * __logf(g_u[i]);  // g
    }
}

// ---------------------------------------------------------------------------
extern "C" void kernel_launch(void* const* d_in, const int* in_sizes, int n_in,
                              void* d_out, int out_size) {
    const float* alpha = (const float*)d_in[0];  // (4, 4096)
    const float* beta  = (const float*)d_in[1];  // (4, 4096)
    const float* C     = (const float*)d_in[2];  // (4096, 4096)
    const float* eps   = (const float*)d_in[3];  // scalar
    float* out = (float*)d_out;                  // f then g

    static bool attr_set = false;
    if (!attr_set) {
        cudaFuncSetAttribute(pass_kernel, cudaFuncAttributeMaxDynamicSharedMemorySize, SMEM_BYTES);
        attr_set = true;
    }

    init_u_kernel<<<(SB * NN + 255) / 256, 256>>>();

    dim3 pb(32, 8), pg(NN / 32, NN / 32);
    prep_kernel<<<pg, pb>>>(C, eps);

    for (int it = 0; it < 10; it++) {
        pass_kernel<<<NN / TR, THREADS, SMEM_BYTES>>>(0, alpha);  // v = alpha / (K  u)
        pass_kernel<<<NN / TR, THREADS, SMEM_BYTES>>>(1, beta);   // u = beta  / (K^T v)
    }

    final_kernel<<<(SB * NN + 255) / 256, 256>>>(out, eps);
}

// round 8
// speedup vs baseline: 2.6360x; 1.4559x over previous
#include <cuda_runtime.h>
#include <cuda_fp16.h>
#include <stdint.h>

#define NN 4096
#define SB 4

// Scratch (allocation-free requirement => __device__ globals)
__device__ __align__(16) __half g_E [(size_t)NN * NN];   // exp(-C/eps)    [n][m]
__device__ __align__(16) __half g_Et[(size_t)NN * NN];   // transpose      [m][n]
__device__ __align__(16) float  g_u [SB * NN];
__device__ __align__(16) float  g_v [SB * NN];

// ---------------------------------------------------------------------------
// u0 = exp(g0/eps) = 1
__global__ void init_u_kernel() {
    int i = blockIdx.x * blockDim.x + threadIdx.x;
    if (i < SB * NN) g_u[i] = 1.0f;
}

// ---------------------------------------------------------------------------
// K = exp(-C/eps) in fp16, plus transposed copy (smem tile transpose).
__global__ __launch_bounds__(256) void prep_kernel(const float* __restrict__ C,
                                                   const float* __restrict__ eps_p) {
    __shared__ __half tile[32][33];
    const float scale = -1.4426950408889634f / eps_p[0];
    const int tx = threadIdx.x, ty = threadIdx.y;
    const int x  = blockIdx.x * 32 + tx;
    const int yb = blockIdx.y * 32;
#pragma unroll
    for (int j = 0; j < 32; j += 8) {
        int y = yb + ty + j;
        float c = __ldg(&C[(size_t)y * NN + x]);
        __half h = __float2half(exp2f(c * scale));
        g_E[(size_t)y * NN + x] = h;
        tile[ty + j][tx] = h;
    }
    __syncthreads();
    const int x2  = blockIdx.y * 32 + tx;
    const int yb2 = blockIdx.x * 32;
#pragma unroll
    for (int j = 0; j < 32; j += 8)
        g_Et[(size_t)(yb2 + ty + j) * NN + x2] = tile[tx][ty + j];
}

// ---------------------------------------------------------------------------
// One Sinkhorn half-step:  xout[s][n] = ab[s][n] / sum_m M[n][m] * xin[s][m]
//
// Direct-LDG, MLP-heavy version. grid=128 blocks x 256 threads; each warp
// register-blocks 4 rows x 4 batches. Per lane-iteration: 4 independent
// uint4 E loads (L1 no-allocate, stays L2-resident across passes) + 8
// float4 u loads (L1-hot), 64 packed fma.rn.f32x2. ~12 KB in flight per
// warp => L2-bandwidth-bound, not latency-bound.
__global__ __launch_bounds__(256, 1) void pass_kernel(int dir, const float* __restrict__ ab) {
    const __half* Mh   = dir ? g_Et : g_E;
    const float*  xin  = dir ? g_v  : g_u;
    float*        xout = dir ? g_u  : g_v;

    const int warp = threadIdx.x >> 5;
    const int lane = threadIdx.x & 31;
    const int row0 = blockIdx.x * 32 + warp * 4;   // 4 rows/warp, 32 rows/block

    const uint4* e0 = reinterpret_cast<const uint4*>(Mh + (size_t)row0 * NN);  // row stride 512 uint4

    unsigned long long acc[4][4];
#pragma unroll
    for (int r = 0; r < 4; r++)
#pragma unroll
        for (int s = 0; s < 4; s++) acc[r][s] = 0ull;

#pragma unroll 2
    for (int it = 0; it < 16; ++it) {
        const int idx = it * 32 + lane;   // uint4 index within row (0..511)
        const int ci  = idx * 8;          // first column of this lane's 8-col strip

        // u pairs: 8 cols x 4 batches, packed as f32x2 per adjacent-column pair
        unsigned long long up[SB][4];
#pragma unroll
        for (int s = 0; s < SB; s++) {
            float4 a = __ldg(reinterpret_cast<const float4*>(xin + s * NN + ci));
            float4 b = __ldg(reinterpret_cast<const float4*>(xin + s * NN + ci + 4));
            asm("mov.b64 %0, {%1, %2};" : "=l"(up[s][0]) : "f"(a.x), "f"(a.y));
            asm("mov.b64 %0, {%1, %2};" : "=l"(up[s][1]) : "f"(a.z), "f"(a.w));
            asm("mov.b64 %0, {%1, %2};" : "=l"(up[s][2]) : "f"(b.x), "f"(b.y));
            asm("mov.b64 %0, {%1, %2};" : "=l"(up[s][3]) : "f"(b.z), "f"(b.w));
        }

#pragma unroll
        for (int r = 0; r < 4; r++) {
            uint4 ev;
            asm("ld.global.nc.L1::no_allocate.v4.u32 {%0,%1,%2,%3}, [%4];"
                : "=r"(ev.x), "=r"(ev.y), "=r"(ev.z), "=r"(ev.w)
                : "l"(e0 + (size_t)r * (NN / 8) + idx));
            uint32_t hw[4] = {ev.x, ev.y, ev.z, ev.w};
#pragma unroll
            for (int p = 0; p < 4; p++) {
                float2 f = __half22float2(*reinterpret_cast<const __half2*>(&hw[p]));
                unsigned long long e2;
                asm("mov.b64 %0, {%1, %2};" : "=l"(e2) : "f"(f.x), "f"(f.y));
#pragma unroll
                for (int s = 0; s < SB; s++)
                    asm("fma.rn.f32x2 %0, %1, %2, %0;" : "+l"(acc[r][s]) : "l"(e2), "l"(up[s][p]));
            }
        }
    }

    // reduce: packed halves, then warp shuffle; fuse the division
#pragma unroll
    for (int r = 0; r < 4; r++) {
#pragma unroll
        for (int s = 0; s < 4; s++) {
            float lo, hi;
            asm("mov.b64 {%0, %1}, %2;" : "=f"(lo), "=f"(hi) : "l"(acc[r][s]));
            float t = lo + hi;
#pragma unroll
            for (int o = 16; o; o >>= 1) t += __shfl_down_sync(0xffffffffu, t, o);
            if (lane == 0) {
                int n = row0 + r;
                xout[s * NN + n] = ab[s * NN + n] / t;
            }
        }
    }
}

// ---------------------------------------------------------------------------
// f = eps*log(v), g = eps*log(u)
__global__ void final_kernel(float* __restrict__ out, const float* __restrict__ eps_p) {
    int i = blockIdx.x * blockDim.x + threadIdx.x;
    float eps = eps_p[0];
    if (i < SB * NN) {
        out[i]           = eps * __logf(g_v[i]);  // f
        out[SB * NN + i] = eps * __logf(g_u[i]);  // g
    }
}

// ---------------------------------------------------------------------------
extern "C" void kernel_launch(void* const* d_in, const int* in_sizes, int n_in,
                              void* d_out, int out_size) {
    const float* alpha = (const float*)d_in[0];  // (4, 4096)
    const float* beta  = (const float*)d_in[1];  // (4, 4096)
    const float* C     = (const float*)d_in[2];  // (4096, 4096)
    const float* eps   = (const float*)d_in[3];  // scalar
    float* out = (float*)d_out;                  // f then g

    init_u_kernel<<<(SB * NN + 255) / 256, 256>>>();

    dim3 pb(32, 8), pg(NN / 32, NN / 32);
    prep_kernel<<<pg, pb>>>(C, eps);

    for (int it = 0; it < 10; it++) {
        pass_kernel<<<NN / 32, 256>>>(0, alpha);  // v = alpha / (K  u)
        pass_kernel<<<NN / 32, 256>>>(1, beta);   // u = beta  / (K^T v)
    }

    final_kernel<<<(SB * NN + 255) / 256, 256>>>(out, eps);
}